// round 3
// baseline (speedup 1.0000x reference)
#include <cuda_runtime.h>
#include <math.h>
#include <stdint.h>

// Problem constants
#define B_    4
#define N_    8192
#define D_    1024
#define DL_   512
#define DH_   4096
#define KSEL  1024
#define NITERS 50
#define EPS_  1.0f
#define KEFF  1152.0f   // min(1024 * 9/8, 8192)

// ---------------- scratch (static device globals; no allocation) ----------------
__device__ float g_s[B_ * N_];
__device__ float g_rscale[B_ * N_];
__device__ int   g_sel[B_ * KSEL];
__device__ float g_w1g[D_ * DL_];          // light_w1 with gamma folded   (2 MB)
__device__ float g_w1hg[D_ * DH_];         // heavy_w1 with gamma folded   (16 MB)
__device__ float g_Hl[16777216];           // light hidden 32768 x 512     (64 MB)
__device__ float g_Hh[16777216];           // heavy hidden 4096 x 4096     (64 MB)

// ---------------- helpers ----------------
__device__ __forceinline__ float gelu_exact(float v) {
    return 0.5f * v * (1.0f + erff(v * 0.7071067811865475f));
}

__device__ __forceinline__ float warpMaxF(float v) {
    #pragma unroll
    for (int o = 16; o > 0; o >>= 1) v = fmaxf(v, __shfl_down_sync(0xffffffffu, v, o));
    return v;
}
__device__ __forceinline__ double warpSumD(double v) {
    #pragma unroll
    for (int o = 16; o > 0; o >>= 1) v += __shfl_down_sync(0xffffffffu, v, o);
    return v;
}
__device__ __forceinline__ int warpSumI(int v) {
    #pragma unroll
    for (int o = 16; o > 0; o >>= 1) v += __shfl_down_sync(0xffffffffu, v, o);
    return v;
}

// Block-wide reduce-max over 1024 threads (32 warps). smf: >=32 floats.
__device__ float blockMaxF(float v, float* smf) {
    int lane = threadIdx.x & 31, wid = threadIdx.x >> 5;
    v = warpMaxF(v);
    __syncthreads();                 // protect smem reuse across calls
    if (lane == 0) smf[wid] = v;
    __syncthreads();
    if (wid == 0) {
        float t = smf[lane];
        t = warpMaxF(t);
        if (lane == 0) smf[0] = t;
    }
    __syncthreads();
    return smf[0];
}

// Block-wide sum (double) over 1024 threads. smd: >=32 doubles.
__device__ double blockSumD(double v, double* smd) {
    int lane = threadIdx.x & 31, wid = threadIdx.x >> 5;
    v = warpSumD(v);
    __syncthreads();
    if (lane == 0) smd[wid] = v;
    __syncthreads();
    if (wid == 0) {
        double t = smd[lane];
        t = warpSumD(t);
        if (lane == 0) smd[0] = t;
    }
    __syncthreads();
    return smd[0];
}

// Block-wide int sum over 1024 threads. smi: >=33 ints.
__device__ int blockSumI(int v, int* smi) {
    int lane = threadIdx.x & 31, wid = threadIdx.x >> 5;
    v = warpSumI(v);
    __syncthreads();
    if (lane == 0) smi[wid] = v;
    __syncthreads();
    if (wid == 0) {
        int t = smi[lane];
        t = warpSumI(t);
        if (lane == 0) smi[32] = t;
    }
    __syncthreads();
    return smi[32];
}

// Block-wide exclusive scan over per-thread values, 1024 threads. smi: >=33 ints.
__device__ int blockScanExclI(int v, int* smi) {
    int lane = threadIdx.x & 31, wid = threadIdx.x >> 5;
    int incl = v;
    #pragma unroll
    for (int o = 1; o < 32; o <<= 1) {
        int t = __shfl_up_sync(0xffffffffu, incl, o);
        if (lane >= o) incl += t;
    }
    __syncthreads();
    if (lane == 31) smi[wid] = incl;
    __syncthreads();
    if (wid == 0) {
        int t = smi[lane];
        int inc2 = t;
        #pragma unroll
        for (int o = 1; o < 32; o <<= 1) {
            int u = __shfl_up_sync(0xffffffffu, inc2, o);
            if (lane >= o) inc2 += u;
        }
        smi[lane] = inc2 - t;   // exclusive warp offsets
    }
    __syncthreads();
    return incl - v + smi[wid];
}

__device__ __forceinline__ unsigned f2ord(float f) {
    unsigned u = __float_as_uint(f);
    return (u & 0x80000000u) ? ~u : (u | 0x80000000u);
}

// ---------------- kernel 0: fold gamma into W1 ----------------
__global__ void fold_gamma_kernel(const float* __restrict__ w, const float* __restrict__ g,
                                  float* __restrict__ o, int N, int total) {
    int i = blockIdx.x * blockDim.x + threadIdx.x;
    if (i < total) o[i] = w[i] * g[i / N];
}

// ---------------- kernel 1: routing score + rms scale, one warp / token ----------------
__global__ void score_norm_kernel(const float* __restrict__ x, const float* __restrict__ rt,
                                  float* __restrict__ s, float* __restrict__ rs) {
    int warp = (blockIdx.x * blockDim.x + threadIdx.x) >> 5;
    int lane = threadIdx.x & 31;
    if (warp >= B_ * N_) return;
    const float4* xr = (const float4*)(x + (size_t)warp * D_);
    const float4* rr = (const float4*)rt;
    float dot = 0.f, ss = 0.f;
    #pragma unroll 4
    for (int i = lane; i < D_ / 4; i += 32) {
        float4 v = xr[i], r = rr[i];
        dot += v.x * r.x + v.y * r.y + v.z * r.z + v.w * r.w;
        ss  += v.x * v.x + v.y * v.y + v.z * v.z + v.w * v.w;
    }
    #pragma unroll
    for (int o = 16; o > 0; o >>= 1) {
        dot += __shfl_down_sync(0xffffffffu, dot, o);
        ss  += __shfl_down_sync(0xffffffffu, ss, o);
    }
    if (lane == 0) {
        s[warp]  = dot;
        rs[warp] = 32.0f / fmaxf(sqrtf(ss), 1e-12f);   // sqrt(1024)=32
    }
}

// ---------------- kernel 2: coordinate descent + exact tie-aware top-k ----------------
// One 1024-thread block per batch row; each thread owns 8 consecutive tokens.
__global__ void __launch_bounds__(1024) router_kernel(const float* __restrict__ s_glob,
                                                      int* __restrict__ sel) {
    __shared__ float  smf[32];
    __shared__ double smd[32];
    __shared__ int    smi[33];
    __shared__ float  a_sh;

    const int tid = threadIdx.x;
    const int b   = blockIdx.x;
    const float* s = s_glob + (size_t)b * N_;

    float sv[8], bv[8];
    #pragma unroll
    for (int i = 0; i < 8; i++) { sv[i] = s[tid * 8 + i]; bv[i] = -sv[i]; }

    const float logk = logf(KEFF);
    const float inv_eps = 1.0f / EPS_;
    float a = 0.f;

    for (int it = 0; it < NITERS; ++it) {
        float m = -INFINITY;
        #pragma unroll
        for (int i = 0; i < 8; i++) m = fmaxf(m, (sv[i] + bv[i]) * inv_eps);
        m = blockMaxF(m, smf);

        double sum = 0.0;
        #pragma unroll
        for (int i = 0; i < 8; i++) sum += (double)expf((sv[i] + bv[i]) * inv_eps - m);
        sum = blockSumD(sum, smd);

        if (tid == 0) a_sh = EPS_ * (logk - (m + (float)log(sum)));
        __syncthreads();
        a = a_sh;
        #pragma unroll
        for (int i = 0; i < 8; i++) bv[i] = -fmaxf(sv[i] + a, 0.0f);
    }

    // Selection key: score = exp(min(s + a, 0)); monotone in key = min(s+a, 0).
    // Saturated tokens (key == 0) all score exactly 1.0 -> top_k ties -> lowest index first.
    unsigned ord[8];
    #pragma unroll
    for (int i = 0; i < 8; i++) {
        float key = fminf(sv[i] + a, 0.0f);
        ord[i] = f2ord(key);
    }

    // Radix-select the KSEL-th largest key (exact, with tie accounting).
    unsigned p = 0; int Cgt = 0;
    for (int bit = 31; bit >= 0; --bit) {
        unsigned cand = (p >> bit) | 1u;
        int c = 0;
        #pragma unroll
        for (int i = 0; i < 8; i++) c += ((ord[i] >> bit) == cand);
        c = blockSumI(c, smi);
        if (Cgt + c >= KSEL) p |= (1u << bit);
        else                 Cgt += c;
    }
    const int need_eq = KSEL - Cgt;   // how many ties at p to take (lowest index first)

    // rank among equal-to-threshold elements (index order)
    int eqc = 0; bool eqf[8];
    #pragma unroll
    for (int i = 0; i < 8; i++) { eqf[i] = (ord[i] == p); eqc += eqf[i] ? 1 : 0; }
    int eq_excl = blockScanExclI(eqc, smi);

    bool self_[8]; int selc = 0; int eqrun = 0;
    #pragma unroll
    for (int i = 0; i < 8; i++) {
        bool sgt = ord[i] > p;
        bool se  = eqf[i] && (eq_excl + eqrun < need_eq);
        eqrun += eqf[i] ? 1 : 0;
        self_[i] = sgt || se;
        selc += self_[i] ? 1 : 0;
    }
    int slot = blockScanExclI(selc, smi);
    #pragma unroll
    for (int i = 0; i < 8; i++) {
        if (self_[i]) { sel[b * KSEL + slot] = b * N_ + tid * 8 + i; slot++; }
    }
}

// ---------------- kernel 3: tiled SGEMM with fused epilogues ----------------
// C[M,N] = op( A[M,K] @ B[K,N] ).  BM=BN=128, BK=8, 256 threads, 8x8 microtile.
// mode 0: store gelu(acc * rscale[arow] + bias[col])        (compact C rows)
// mode 1: store acc + bias[col]                             (direct rows)
// mode 2: C[cmap[row]] += acc + bias[col]                   (scatter-accumulate)
__global__ void __launch_bounds__(256) sgemm_kernel(
    const float* __restrict__ A, const float* __restrict__ B,
    float* __restrict__ C, const float* __restrict__ bias,
    const float* __restrict__ rscale,
    const int* __restrict__ amap, const int* __restrict__ cmap,
    int M, int N, int K, int mode)
{
    __shared__ float As[8][128];
    __shared__ float Bs[8][128];

    const int tid = threadIdx.x;
    const int bx = blockIdx.x, by = blockIdx.y;

    // A tile loader: 128 rows x 8 cols per step; one float4 per thread.
    const int aRow = tid >> 1;
    const int aCol = (tid & 1) << 2;
    const int aGrow = by * 128 + aRow;
    const int aIdx  = amap ? amap[aGrow] : aGrow;
    const float* Ap = A + (size_t)aIdx * K + aCol;

    // B tile loader: 8 rows x 128 cols; one float4 per thread.
    const int bRow = tid >> 5;
    const int bCol = (tid & 31) << 2;
    const float* Bp = B + (size_t)bRow * N + (size_t)bx * 128 + bCol;

    float acc[8][8];
    #pragma unroll
    for (int i = 0; i < 8; i++)
        #pragma unroll
        for (int j = 0; j < 8; j++) acc[i][j] = 0.f;

    const int tx = tid & 15, ty = tid >> 4;

    for (int k0 = 0; k0 < K; k0 += 8) {
        float4 av = *(const float4*)(Ap + k0);
        float4 bv = *(const float4*)(Bp + (size_t)k0 * N);
        As[aCol + 0][aRow] = av.x;
        As[aCol + 1][aRow] = av.y;
        As[aCol + 2][aRow] = av.z;
        As[aCol + 3][aRow] = av.w;
        *(float4*)(&Bs[bRow][bCol]) = bv;
        __syncthreads();
        #pragma unroll
        for (int kk = 0; kk < 8; kk++) {
            float4 a0 = *(const float4*)(&As[kk][ty * 8]);
            float4 a1 = *(const float4*)(&As[kk][ty * 8 + 4]);
            float4 b0 = *(const float4*)(&Bs[kk][tx * 8]);
            float4 b1 = *(const float4*)(&Bs[kk][tx * 8 + 4]);
            float ar[8] = {a0.x, a0.y, a0.z, a0.w, a1.x, a1.y, a1.z, a1.w};
            float br[8] = {b0.x, b0.y, b0.z, b0.w, b1.x, b1.y, b1.z, b1.w};
            #pragma unroll
            for (int i = 0; i < 8; i++)
                #pragma unroll
                for (int j = 0; j < 8; j++)
                    acc[i][j] = fmaf(ar[i], br[j], acc[i][j]);
        }
        __syncthreads();
    }

    const int rowBase = by * 128 + ty * 8;
    const int colBase = bx * 128 + tx * 8;

    if (mode == 0) {
        #pragma unroll
        for (int i = 0; i < 8; i++) {
            int row  = rowBase + i;
            int xrow = amap ? amap[row] : row;
            float r  = rscale[xrow];
            float* cp = C + (size_t)row * N + colBase;
            #pragma unroll
            for (int j = 0; j < 8; j++) {
                float v = fmaf(acc[i][j], r, bias[colBase + j]);
                cp[j] = gelu_exact(v);
            }
        }
    } else if (mode == 1) {
        #pragma unroll
        for (int i = 0; i < 8; i++) {
            float* cp = C + (size_t)(rowBase + i) * N + colBase;
            #pragma unroll
            for (int j = 0; j < 8; j++) cp[j] = acc[i][j] + bias[colBase + j];
        }
    } else {
        #pragma unroll
        for (int i = 0; i < 8; i++) {
            int orow = cmap[rowBase + i];
            float* cp = C + (size_t)orow * N + colBase;
            #pragma unroll
            for (int j = 0; j < 8; j++) cp[j] += acc[i][j] + bias[colBase + j];
        }
    }
}

// ---------------- launch ----------------
extern "C" void kernel_launch(void* const* d_in, const int* in_sizes, int n_in,
                              void* d_out, int out_size) {
    const float* x      = (const float*)d_in[0];
    const float* rt     = (const float*)d_in[1];
    const float* lgam   = (const float*)d_in[2];
    const float* lw1    = (const float*)d_in[3];
    const float* lb1    = (const float*)d_in[4];
    const float* lw2    = (const float*)d_in[5];
    const float* lb2    = (const float*)d_in[6];
    const float* hgam   = (const float*)d_in[7];
    const float* hw1    = (const float*)d_in[8];
    const float* hb1    = (const float*)d_in[9];
    const float* hw2    = (const float*)d_in[10];
    const float* hb2    = (const float*)d_in[11];
    float* out = (float*)d_out;

    void *s_p, *rs_p, *sel_p, *w1g_p, *w1hg_p, *Hl_p, *Hh_p;
    cudaGetSymbolAddress(&s_p,    g_s);
    cudaGetSymbolAddress(&rs_p,   g_rscale);
    cudaGetSymbolAddress(&sel_p,  g_sel);
    cudaGetSymbolAddress(&w1g_p,  g_w1g);
    cudaGetSymbolAddress(&w1hg_p, g_w1hg);
    cudaGetSymbolAddress(&Hl_p,   g_Hl);
    cudaGetSymbolAddress(&Hh_p,   g_Hh);

    // fold gamma into W1 (light and heavy)
    {
        int totL = D_ * DL_;
        fold_gamma_kernel<<<(totL + 255) / 256, 256>>>(lw1, lgam, (float*)w1g_p, DL_, totL);
        int totH = D_ * DH_;
        fold_gamma_kernel<<<(totH + 255) / 256, 256>>>(hw1, hgam, (float*)w1hg_p, DH_, totH);
    }

    // routing scores + rms scales (one warp per token)
    score_norm_kernel<<<(B_ * N_) / 8, 256>>>(x, rt, (float*)s_p, (float*)rs_p);

    // coordinate descent + top-k selection (one block per batch row)
    router_kernel<<<B_, 1024>>>((const float*)s_p, (int*)sel_p);

    // light branch: H = gelu(rms(x) @ (gamma*W1) + b1);  out = H @ W2 + b2
    sgemm_kernel<<<dim3(DL_ / 128, (B_ * N_) / 128), 256>>>(
        x, (const float*)w1g_p, (float*)Hl_p, lb1, (const float*)rs_p,
        nullptr, nullptr, B_ * N_, DL_, D_, 0);
    sgemm_kernel<<<dim3(D_ / 128, (B_ * N_) / 128), 256>>>(
        (const float*)Hl_p, lw2, out, lb2, nullptr,
        nullptr, nullptr, B_ * N_, D_, DL_, 1);

    // heavy branch on gathered tokens; scatter-accumulate into out
    sgemm_kernel<<<dim3(DH_ / 128, (B_ * KSEL) / 128), 256>>>(
        x, (const float*)w1hg_p, (float*)Hh_p, hb1, (const float*)rs_p,
        (const int*)sel_p, nullptr, B_ * KSEL, DH_, D_, 0);
    sgemm_kernel<<<dim3(D_ / 128, (B_ * KSEL) / 128), 256>>>(
        (const float*)Hh_p, hw2, out, hb2, nullptr,
        nullptr, (const int*)sel_p, B_ * KSEL, D_, DH_, 2);
}

// round 5
// speedup vs baseline: 1.8306x; 1.8306x over previous
#include <cuda_runtime.h>
#include <cuda_bf16.h>
#include <math.h>
#include <stdint.h>

#define B_    4
#define N_    8192
#define D_    1024
#define DL_   512
#define DH_   4096
#define KSEL  1024
#define NITERS 50
#define EPS_  1.0f
#define KEFF  1152.0f

// ---------------- scratch (static device globals; no allocation) ----------------
__device__ float g_s[B_ * N_];
__device__ int   g_sel[B_ * KSEL];
__device__ __align__(128) __nv_bfloat16 g_xhi[B_ * N_ * D_];
__device__ __align__(128) __nv_bfloat16 g_xlo[B_ * N_ * D_];
__device__ __align__(128) __nv_bfloat16 g_w1l_hi[DL_ * D_], g_w1l_lo[DL_ * D_];
__device__ __align__(128) __nv_bfloat16 g_w2l_hi[D_ * DL_], g_w2l_lo[D_ * DL_];
__device__ __align__(128) __nv_bfloat16 g_w1h_hi[DH_ * D_], g_w1h_lo[DH_ * D_];
__device__ __align__(128) __nv_bfloat16 g_w2h_hi[D_ * DH_], g_w2h_lo[D_ * DH_];
__device__ __align__(128) __nv_bfloat16 g_hl_hi[B_ * N_ * DL_], g_hl_lo[B_ * N_ * DL_];
__device__ __align__(128) __nv_bfloat16 g_hh_hi[B_ * KSEL * DH_], g_hh_lo[B_ * KSEL * DH_];

// ---------------- PTX helpers (base sm_100 target ONLY: cp.async / ldmatrix / mma.sync) ----
__device__ __forceinline__ uint32_t smem_u32(const void* p) {
    uint32_t a;
    asm("{ .reg .u64 t; cvta.to.shared.u64 t, %1; cvt.u32.u64 %0, t; }" : "=r"(a) : "l"(p));
    return a;
}
__device__ __forceinline__ void cpa16(uint32_t dst, const void* src) {
    asm volatile("cp.async.cg.shared.global [%0], [%1], 16;" :: "r"(dst), "l"(src));
}
#define CP_COMMIT() asm volatile("cp.async.commit_group;" ::: "memory")
__device__ __forceinline__ void cp_wait0() { asm volatile("cp.async.wait_group 0;" ::: "memory"); }
__device__ __forceinline__ void cp_wait1() { asm volatile("cp.async.wait_group 1;" ::: "memory"); }

#define LDSM4(r, addr) \
    asm volatile("ldmatrix.sync.aligned.m8n8.x4.shared.b16 {%0,%1,%2,%3}, [%4];" \
        : "=r"((r)[0]), "=r"((r)[1]), "=r"((r)[2]), "=r"((r)[3]) : "r"(addr))

#define MMA16816(c, a, b0, b1) \
    asm volatile("mma.sync.aligned.m16n8k16.row.col.f32.bf16.bf16.f32 " \
        "{%0,%1,%2,%3}, {%4,%5,%6,%7}, {%8,%9}, {%0,%1,%2,%3};" \
        : "+f"((c)[0]), "+f"((c)[1]), "+f"((c)[2]), "+f"((c)[3]) \
        : "r"((a)[0]), "r"((a)[1]), "r"((a)[2]), "r"((a)[3]), "r"(b0), "r"(b1))

__device__ __forceinline__ float gelu_exact(float v) {
    return 0.5f * v * (1.0f + erff(v * 0.7071067811865475f));
}

// ---------------- router reductions (unchanged from passing version) ----------------
__device__ __forceinline__ float warpMaxF(float v) {
    #pragma unroll
    for (int o = 16; o > 0; o >>= 1) v = fmaxf(v, __shfl_down_sync(0xffffffffu, v, o));
    return v;
}
__device__ __forceinline__ double warpSumD(double v) {
    #pragma unroll
    for (int o = 16; o > 0; o >>= 1) v += __shfl_down_sync(0xffffffffu, v, o);
    return v;
}
__device__ __forceinline__ int warpSumI(int v) {
    #pragma unroll
    for (int o = 16; o > 0; o >>= 1) v += __shfl_down_sync(0xffffffffu, v, o);
    return v;
}
__device__ float blockMaxF(float v, float* smf) {
    int lane = threadIdx.x & 31, wid = threadIdx.x >> 5;
    v = warpMaxF(v);
    __syncthreads();
    if (lane == 0) smf[wid] = v;
    __syncthreads();
    if (wid == 0) { float t = smf[lane]; t = warpMaxF(t); if (lane == 0) smf[0] = t; }
    __syncthreads();
    return smf[0];
}
__device__ double blockSumD(double v, double* smd) {
    int lane = threadIdx.x & 31, wid = threadIdx.x >> 5;
    v = warpSumD(v);
    __syncthreads();
    if (lane == 0) smd[wid] = v;
    __syncthreads();
    if (wid == 0) { double t = smd[lane]; t = warpSumD(t); if (lane == 0) smd[0] = t; }
    __syncthreads();
    return smd[0];
}
__device__ int blockSumI(int v, int* smi) {
    int lane = threadIdx.x & 31, wid = threadIdx.x >> 5;
    v = warpSumI(v);
    __syncthreads();
    if (lane == 0) smi[wid] = v;
    __syncthreads();
    if (wid == 0) { int t = smi[lane]; t = warpSumI(t); if (lane == 0) smi[32] = t; }
    __syncthreads();
    return smi[32];
}
__device__ int blockScanExclI(int v, int* smi) {
    int lane = threadIdx.x & 31, wid = threadIdx.x >> 5;
    int incl = v;
    #pragma unroll
    for (int o = 1; o < 32; o <<= 1) {
        int t = __shfl_up_sync(0xffffffffu, incl, o);
        if (lane >= o) incl += t;
    }
    __syncthreads();
    if (lane == 31) smi[wid] = incl;
    __syncthreads();
    if (wid == 0) {
        int t = smi[lane];
        int inc2 = t;
        #pragma unroll
        for (int o = 1; o < 32; o <<= 1) {
            int u = __shfl_up_sync(0xffffffffu, inc2, o);
            if (lane >= o) inc2 += u;
        }
        smi[lane] = inc2 - t;
    }
    __syncthreads();
    return incl - v + smi[wid];
}
__device__ __forceinline__ unsigned f2ord(float f) {
    unsigned u = __float_as_uint(f);
    return (u & 0x80000000u) ? ~u : (u | 0x80000000u);
}

// ---------------- kernel: fused score + normalize + bf16 split (warp per token) ----------------
__global__ void convert_kernel(const float* __restrict__ x, const float* __restrict__ rt,
                               float* __restrict__ s) {
    int token = (blockIdx.x * blockDim.x + threadIdx.x) >> 5;
    int lane = threadIdx.x & 31;
    if (token >= B_ * N_) return;
    const float4* xr = (const float4*)(x + (size_t)token * D_);
    const float4* rr = (const float4*)rt;
    float4 v[8]; float dot = 0.f, ss = 0.f;
    #pragma unroll
    for (int i = 0; i < 8; i++) {
        v[i] = xr[lane + 32 * i];
        float4 r = rr[lane + 32 * i];
        dot += v[i].x * r.x + v[i].y * r.y + v[i].z * r.z + v[i].w * r.w;
        ss  += v[i].x * v[i].x + v[i].y * v[i].y + v[i].z * v[i].z + v[i].w * v[i].w;
    }
    #pragma unroll
    for (int o = 16; o > 0; o >>= 1) {
        dot += __shfl_down_sync(0xffffffffu, dot, o);
        ss  += __shfl_xor_sync(0xffffffffu, ss, o);
    }
    if (lane == 0) s[token] = dot;
    float sc = 32.0f / fmaxf(sqrtf(ss), 1e-12f);
    __nv_bfloat162* ph = (__nv_bfloat162*)(g_xhi + (size_t)token * D_);
    __nv_bfloat162* pl = (__nv_bfloat162*)(g_xlo + (size_t)token * D_);
    #pragma unroll
    for (int i = 0; i < 8; i++) {
        int e = lane + 32 * i;
        float a0 = v[i].x * sc, a1 = v[i].y * sc, a2 = v[i].z * sc, a3 = v[i].w * sc;
        __nv_bfloat162 h0, h1, l0, l1;
        h0.x = __float2bfloat16(a0); h0.y = __float2bfloat16(a1);
        h1.x = __float2bfloat16(a2); h1.y = __float2bfloat16(a3);
        l0.x = __float2bfloat16(a0 - __bfloat162float(h0.x));
        l0.y = __float2bfloat16(a1 - __bfloat162float(h0.y));
        l1.x = __float2bfloat16(a2 - __bfloat162float(h1.x));
        l1.y = __float2bfloat16(a3 - __bfloat162float(h1.y));
        ph[2 * e] = h0; ph[2 * e + 1] = h1;
        pl[2 * e] = l0; pl[2 * e + 1] = l1;
    }
}

// ---------------- kernel: weight transpose + gamma fold + split ----------------
__global__ void wsplit_kernel(const float* __restrict__ W, const float* __restrict__ gamma,
                              __nv_bfloat16* __restrict__ Thi, __nv_bfloat16* __restrict__ Tlo,
                              int K, int N) {
    __shared__ float t[32][33];
    int n0 = blockIdx.x * 32, k0 = blockIdx.y * 32;
    int tx = threadIdx.x, ty = threadIdx.y;
    #pragma unroll
    for (int j = 0; j < 4; j++) {
        int k = k0 + ty + j * 8;
        float g = gamma ? gamma[k] : 1.0f;
        t[ty + j * 8][tx] = W[(size_t)k * N + n0 + tx] * g;
    }
    __syncthreads();
    #pragma unroll
    for (int j = 0; j < 4; j++) {
        int n = n0 + ty + j * 8;
        float v = t[tx][ty + j * 8];
        __nv_bfloat16 h = __float2bfloat16(v);
        Thi[(size_t)n * K + k0 + tx] = h;
        Tlo[(size_t)n * K + k0 + tx] = __float2bfloat16(v - __bfloat162float(h));
    }
}

// ---------------- kernel: coordinate descent + exact tie-aware top-k ----------------
__global__ void __launch_bounds__(1024) router_kernel(const float* __restrict__ s_glob,
                                                      int* __restrict__ sel) {
    __shared__ float  smf[32];
    __shared__ double smd[32];
    __shared__ int    smi[33];
    __shared__ float  a_sh;
    const int tid = threadIdx.x;
    const int b   = blockIdx.x;
    const float* s = s_glob + (size_t)b * N_;

    float sv[8], bv[8];
    #pragma unroll
    for (int i = 0; i < 8; i++) { sv[i] = s[tid * 8 + i]; bv[i] = -sv[i]; }

    const float logk = logf(KEFF);
    float a = 0.f;
    for (int it = 0; it < NITERS; ++it) {
        float m = -INFINITY;
        #pragma unroll
        for (int i = 0; i < 8; i++) m = fmaxf(m, sv[i] + bv[i]);
        m = blockMaxF(m, smf);
        double sum = 0.0;
        #pragma unroll
        for (int i = 0; i < 8; i++) sum += (double)expf(sv[i] + bv[i] - m);
        sum = blockSumD(sum, smd);
        if (tid == 0) a_sh = EPS_ * (logk - (m + (float)log(sum)));
        __syncthreads();
        a = a_sh;
        #pragma unroll
        for (int i = 0; i < 8; i++) bv[i] = -fmaxf(sv[i] + a, 0.0f);
    }

    unsigned ord[8];
    #pragma unroll
    for (int i = 0; i < 8; i++) ord[i] = f2ord(fminf(sv[i] + a, 0.0f));

    unsigned p = 0; int Cgt = 0;
    for (int bit = 31; bit >= 0; --bit) {
        unsigned cand = (p >> bit) | 1u;
        int c = 0;
        #pragma unroll
        for (int i = 0; i < 8; i++) c += ((ord[i] >> bit) == cand);
        c = blockSumI(c, smi);
        if (Cgt + c >= KSEL) p |= (1u << bit);
        else                 Cgt += c;
    }
    const int need_eq = KSEL - Cgt;
    int eqc = 0; bool eqf[8];
    #pragma unroll
    for (int i = 0; i < 8; i++) { eqf[i] = (ord[i] == p); eqc += eqf[i] ? 1 : 0; }
    int eq_excl = blockScanExclI(eqc, smi);
    bool self_[8]; int selc = 0; int eqrun = 0;
    #pragma unroll
    for (int i = 0; i < 8; i++) {
        bool sgt = ord[i] > p;
        bool se  = eqf[i] && (eq_excl + eqrun < need_eq);
        eqrun += eqf[i] ? 1 : 0;
        self_[i] = sgt || se;
        selc += self_[i] ? 1 : 0;
    }
    int slot = blockScanExclI(selc, smi);
    #pragma unroll
    for (int i = 0; i < 8; i++)
        if (self_[i]) { sel[b * KSEL + slot] = b * N_ + tid * 8 + i; slot++; }
}

// ---------------- mma.sync split-bf16 GEMM ----------------
// CTA tile 128x128, BK=64, 2-stage cp.async pipeline.
// SMEM stage layout (144B padded rows): Ahi[128] | Alo[128] | Bhi[128] | Blo[128]
// A: [M][K] row-major bf16 (hi/lo). B: [N][K] row-major bf16 (hi/lo).
// D = Ahi*Bhi + Ahi*Blo + Alo*Bhi (fp32 accum).
// mode 0: OHi/OLo[row,col] = split(gelu(acc+bias))
// mode 1: OF[row*1024+col] = acc+bias
// mode 2: OF[cmap[row]*1024+col] += acc+bias
#define ROWB  144u
#define STG2  73728u           // 512 * 144
#define GSM2  (2u * STG2)

__global__ void __launch_bounds__(256) gemm_mma(
    const __nv_bfloat16* __restrict__ Ahi, const __nv_bfloat16* __restrict__ Alo,
    const __nv_bfloat16* __restrict__ Bhi, const __nv_bfloat16* __restrict__ Blo,
    int K, const int* __restrict__ amap,
    const float* __restrict__ bias, int mode,
    __nv_bfloat16* __restrict__ OHi, __nv_bfloat16* __restrict__ OLo, int NldH,
    float* __restrict__ OF, const int* __restrict__ cmap)
{
    extern __shared__ char smraw[];
    const uint32_t smb = smem_u32(smraw);
    const int tid = threadIdx.x;
    const int lane = tid & 31, wid = tid >> 5;
    const int mwarp = wid >> 1, nwarp = wid & 1;    // warp grid 4(M) x 2(N)

    // ---- loader setup: 512 rows, 2 per thread ----
    const char* src[2]; uint32_t dst[2];
    #pragma unroll
    for (int j = 0; j < 2; j++) {
        int r = tid + j * 256;
        int op = r >> 7, rr = r & 127;
        const __nv_bfloat16* base; int grow;
        if (op < 2) {
            grow = blockIdx.y * 128 + rr;
            if (amap) grow = amap[grow];
            base = op ? Alo : Ahi;
        } else {
            grow = blockIdx.x * 128 + rr;
            base = (op == 3) ? Blo : Bhi;
        }
        src[j] = (const char*)(base + (size_t)grow * K);
        dst[j] = smb + (uint32_t)r * ROWB;
    }

    #define LD_CHUNK(kc, stoff) do { \
        _Pragma("unroll") for (int j_ = 0; j_ < 2; j_++) { \
            const char* s_ = src[j_] + (size_t)(kc) * 128; \
            uint32_t d_ = dst[j_] + (stoff); \
            _Pragma("unroll") for (int c_ = 0; c_ < 8; c_++) \
                cpa16(d_ + c_ * 16u, s_ + c_ * 16); \
        } \
        CP_COMMIT(); \
    } while (0)

    // ldmatrix lane-address components (within a stage)
    const uint32_t aoff = (uint32_t)((mwarp * 32 + (lane & 7) + ((lane >> 3) & 1) * 8) * ROWB
                                     + (lane >> 4) * 16);
    const uint32_t boff = (uint32_t)((nwarp * 64 + (lane >> 4) * 8 + (lane & 7)) * ROWB
                                     + ((lane >> 3) & 1) * 16);

    float acc[2][8][4];
    #pragma unroll
    for (int mt = 0; mt < 2; mt++)
        #pragma unroll
        for (int nt = 0; nt < 8; nt++)
            #pragma unroll
            for (int q = 0; q < 4; q++) acc[mt][nt][q] = 0.f;

    const int nk = K >> 6;
    LD_CHUNK(0, 0u);
    LD_CHUNK(1, STG2);

    for (int it = 0; it < nk; ++it) {
        if (it + 1 < nk) cp_wait1(); else cp_wait0();
        __syncthreads();
        const uint32_t st = smb + (uint32_t)(it & 1) * STG2;
        #pragma unroll
        for (int ks = 0; ks < 4; ks++) {
            const uint32_t kb = (uint32_t)ks * 32u;
            uint32_t ah[2][4], al[2][4];
            #pragma unroll
            for (int mt = 0; mt < 2; mt++) {
                LDSM4(ah[mt], st + (uint32_t)mt * (16u * ROWB) + kb + aoff);
                LDSM4(al[mt], st + 18432u + (uint32_t)mt * (16u * ROWB) + kb + aoff);
            }
            uint32_t bh[4][4], bl[4][4];
            #pragma unroll
            for (int jp = 0; jp < 4; jp++) {
                LDSM4(bh[jp], st + 36864u + (uint32_t)jp * (16u * ROWB) + kb + boff);
                LDSM4(bl[jp], st + 55296u + (uint32_t)jp * (16u * ROWB) + kb + boff);
            }
            #pragma unroll
            for (int mt = 0; mt < 2; mt++)
                #pragma unroll
                for (int nt = 0; nt < 8; nt++) {
                    const int jp = nt >> 1, sl = (nt & 1) * 2;
                    MMA16816(acc[mt][nt], ah[mt], bh[jp][sl], bh[jp][sl + 1]);
                    MMA16816(acc[mt][nt], ah[mt], bl[jp][sl], bl[jp][sl + 1]);
                    MMA16816(acc[mt][nt], al[mt], bh[jp][sl], bh[jp][sl + 1]);
                }
        }
        __syncthreads();
        if (it + 2 < nk) LD_CHUNK(it + 2, (uint32_t)(it & 1) * STG2);
    }

    // ---- epilogue ----
    const int mbase = mwarp * 32, nbase = nwarp * 64;
    #pragma unroll
    for (int mt = 0; mt < 2; mt++) {
        #pragma unroll
        for (int half = 0; half < 2; half++) {
            const int row  = mbase + mt * 16 + (lane >> 2) + half * 8;
            const int grow = blockIdx.y * 128 + row;
            if (mode == 0) {
                size_t obase = (size_t)grow * NldH;
                #pragma unroll
                for (int nt = 0; nt < 8; nt++) {
                    const int gc = blockIdx.x * 128 + nbase + nt * 8 + (lane & 3) * 2;
                    float v0 = acc[mt][nt][half * 2 + 0] + __ldg(&bias[gc]);
                    float v1 = acc[mt][nt][half * 2 + 1] + __ldg(&bias[gc + 1]);
                    float g0 = gelu_exact(v0), g1 = gelu_exact(v1);
                    __nv_bfloat162 h2, l2;
                    h2.x = __float2bfloat16(g0); h2.y = __float2bfloat16(g1);
                    l2.x = __float2bfloat16(g0 - __bfloat162float(h2.x));
                    l2.y = __float2bfloat16(g1 - __bfloat162float(h2.y));
                    *(__nv_bfloat162*)(OHi + obase + gc) = h2;
                    *(__nv_bfloat162*)(OLo + obase + gc) = l2;
                }
            } else if (mode == 1) {
                float* po = OF + (size_t)grow * 1024;
                #pragma unroll
                for (int nt = 0; nt < 8; nt++) {
                    const int gc = blockIdx.x * 128 + nbase + nt * 8 + (lane & 3) * 2;
                    float2 w;
                    w.x = acc[mt][nt][half * 2 + 0] + __ldg(&bias[gc]);
                    w.y = acc[mt][nt][half * 2 + 1] + __ldg(&bias[gc + 1]);
                    *(float2*)(po + gc) = w;
                }
            } else {
                const int orow = cmap[grow];
                float* po = OF + (size_t)orow * 1024;
                #pragma unroll
                for (int nt = 0; nt < 8; nt++) {
                    const int gc = blockIdx.x * 128 + nbase + nt * 8 + (lane & 3) * 2;
                    float2 o = *(float2*)(po + gc);
                    o.x += acc[mt][nt][half * 2 + 0] + __ldg(&bias[gc]);
                    o.y += acc[mt][nt][half * 2 + 1] + __ldg(&bias[gc + 1]);
                    *(float2*)(po + gc) = o;
                }
            }
        }
    }
    #undef LD_CHUNK
}

// ---------------- launch ----------------
extern "C" void kernel_launch(void* const* d_in, const int* in_sizes, int n_in,
                              void* d_out, int out_size) {
    const float* x    = (const float*)d_in[0];
    const float* rt   = (const float*)d_in[1];
    const float* lgam = (const float*)d_in[2];
    const float* lw1  = (const float*)d_in[3];
    const float* lb1  = (const float*)d_in[4];
    const float* lw2  = (const float*)d_in[5];
    const float* lb2  = (const float*)d_in[6];
    const float* hgam = (const float*)d_in[7];
    const float* hw1  = (const float*)d_in[8];
    const float* hb1  = (const float*)d_in[9];
    const float* hw2  = (const float*)d_in[10];
    const float* hb2  = (const float*)d_in[11];
    float* out = (float*)d_out;

    cudaFuncSetAttribute(gemm_mma, cudaFuncAttributeMaxDynamicSharedMemorySize, GSM2);

    void *s_p, *sel_p, *xhi, *xlo, *w1lh, *w1ll, *w2lh, *w2ll, *w1hh, *w1hl, *w2hh, *w2hl,
         *hlh, *hll, *hhh, *hhl;
    cudaGetSymbolAddress(&s_p, g_s);       cudaGetSymbolAddress(&sel_p, g_sel);
    cudaGetSymbolAddress(&xhi, g_xhi);     cudaGetSymbolAddress(&xlo, g_xlo);
    cudaGetSymbolAddress(&w1lh, g_w1l_hi); cudaGetSymbolAddress(&w1ll, g_w1l_lo);
    cudaGetSymbolAddress(&w2lh, g_w2l_hi); cudaGetSymbolAddress(&w2ll, g_w2l_lo);
    cudaGetSymbolAddress(&w1hh, g_w1h_hi); cudaGetSymbolAddress(&w1hl, g_w1h_lo);
    cudaGetSymbolAddress(&w2hh, g_w2h_hi); cudaGetSymbolAddress(&w2hl, g_w2h_lo);
    cudaGetSymbolAddress(&hlh, g_hl_hi);   cudaGetSymbolAddress(&hll, g_hl_lo);
    cudaGetSymbolAddress(&hhh, g_hh_hi);   cudaGetSymbolAddress(&hhl, g_hh_lo);

    dim3 wb(32, 8);
    wsplit_kernel<<<dim3(DL_/32, D_/32), wb>>>(lw1, lgam, (__nv_bfloat16*)w1lh, (__nv_bfloat16*)w1ll, D_, DL_);
    wsplit_kernel<<<dim3(D_/32, DL_/32), wb>>>(lw2, nullptr, (__nv_bfloat16*)w2lh, (__nv_bfloat16*)w2ll, DL_, D_);
    wsplit_kernel<<<dim3(DH_/32, D_/32), wb>>>(hw1, hgam, (__nv_bfloat16*)w1hh, (__nv_bfloat16*)w1hl, D_, DH_);
    wsplit_kernel<<<dim3(D_/32, DH_/32), wb>>>(hw2, nullptr, (__nv_bfloat16*)w2hh, (__nv_bfloat16*)w2hl, DH_, D_);

    convert_kernel<<<(B_ * N_) / 8, 256>>>(x, rt, (float*)s_p);
    router_kernel<<<B_, 1024>>>((const float*)s_p, (int*)sel_p);

    // light: hidden = gelu(xn @ (g*W1) + b1); out = hidden @ W2 + b2
    gemm_mma<<<dim3(DL_/128, (B_*N_)/128), 256, GSM2>>>(
        (__nv_bfloat16*)xhi, (__nv_bfloat16*)xlo, (__nv_bfloat16*)w1lh, (__nv_bfloat16*)w1ll,
        D_, nullptr, lb1, 0, (__nv_bfloat16*)hlh, (__nv_bfloat16*)hll, DL_, nullptr, nullptr);
    gemm_mma<<<dim3(D_/128, (B_*N_)/128), 256, GSM2>>>(
        (__nv_bfloat16*)hlh, (__nv_bfloat16*)hll, (__nv_bfloat16*)w2lh, (__nv_bfloat16*)w2ll,
        DL_, nullptr, lb2, 1, nullptr, nullptr, 0, out, nullptr);

    // heavy: gathered rows -> hidden -> scatter-accumulate into out
    gemm_mma<<<dim3(DH_/128, (B_*KSEL)/128), 256, GSM2>>>(
        (__nv_bfloat16*)xhi, (__nv_bfloat16*)xlo, (__nv_bfloat16*)w1hh, (__nv_bfloat16*)w1hl,
        D_, (const int*)sel_p, hb1, 0, (__nv_bfloat16*)hhh, (__nv_bfloat16*)hhl, DH_, nullptr, nullptr);
    gemm_mma<<<dim3(D_/128, (B_*KSEL)/128), 256, GSM2>>>(
        (__nv_bfloat16*)hhh, (__nv_bfloat16*)hhl, (__nv_bfloat16*)w2hh, (__nv_bfloat16*)w2hl,
        DH_, nullptr, hb2, 2, nullptr, nullptr, 0, out, (const int*)sel_p);
}

// round 6
// speedup vs baseline: 1.9899x; 1.0870x over previous
#include <cuda_runtime.h>
#include <cuda_bf16.h>
#include <math.h>
#include <stdint.h>

#define B_    4
#define N_    8192
#define D_    1024
#define DL_   512
#define DH_   4096
#define KSEL  1024
#define NITERS 50
#define EPS_  1.0f
#define KEFF  1152.0f

// ---------------- scratch (static device globals; no allocation) ----------------
__device__ float g_s[B_ * N_];
__device__ int   g_sel[B_ * KSEL];
__device__ __align__(128) __nv_bfloat16 g_xhi[B_ * N_ * D_];
__device__ __align__(128) __nv_bfloat16 g_xlo[B_ * N_ * D_];
__device__ __align__(128) __nv_bfloat16 g_w1l_hi[DL_ * D_], g_w1l_lo[DL_ * D_];
__device__ __align__(128) __nv_bfloat16 g_w2l_hi[D_ * DL_], g_w2l_lo[D_ * DL_];
__device__ __align__(128) __nv_bfloat16 g_w1h_hi[DH_ * D_], g_w1h_lo[DH_ * D_];
__device__ __align__(128) __nv_bfloat16 g_w2h_hi[D_ * DH_], g_w2h_lo[D_ * DH_];
__device__ __align__(128) __nv_bfloat16 g_hl_hi[B_ * N_ * DL_], g_hl_lo[B_ * N_ * DL_];
__device__ __align__(128) __nv_bfloat16 g_hh_hi[B_ * KSEL * DH_], g_hh_lo[B_ * KSEL * DH_];

// ---------------- PTX helpers (base-target only: cp.async / ldmatrix / mma.sync) ----
__device__ __forceinline__ uint32_t smem_u32(const void* p) {
    uint32_t a;
    asm("{ .reg .u64 t; cvta.to.shared.u64 t, %1; cvt.u32.u64 %0, t; }" : "=r"(a) : "l"(p));
    return a;
}
__device__ __forceinline__ void cpa16(uint32_t dst, const void* src) {
    asm volatile("cp.async.cg.shared.global [%0], [%1], 16;" :: "r"(dst), "l"(src));
}
#define CP_COMMIT() asm volatile("cp.async.commit_group;" ::: "memory")
__device__ __forceinline__ void cp_wait0() { asm volatile("cp.async.wait_group 0;" ::: "memory"); }
__device__ __forceinline__ void cp_wait1() { asm volatile("cp.async.wait_group 1;" ::: "memory"); }

#define LDSM4(r, addr) \
    asm volatile("ldmatrix.sync.aligned.m8n8.x4.shared.b16 {%0,%1,%2,%3}, [%4];" \
        : "=r"((r)[0]), "=r"((r)[1]), "=r"((r)[2]), "=r"((r)[3]) : "r"(addr))

#define MMA16816(c, a, b0, b1) \
    asm volatile("mma.sync.aligned.m16n8k16.row.col.f32.bf16.bf16.f32 " \
        "{%0,%1,%2,%3}, {%4,%5,%6,%7}, {%8,%9}, {%0,%1,%2,%3};" \
        : "+f"((c)[0]), "+f"((c)[1]), "+f"((c)[2]), "+f"((c)[3]) \
        : "r"((a)[0]), "r"((a)[1]), "r"((a)[2]), "r"((a)[3]), "r"(b0), "r"(b1))

__device__ __forceinline__ float gelu_exact(float v) {
    return 0.5f * v * (1.0f + erff(v * 0.7071067811865475f));
}

// ---------------- reductions (512-thread router: 16 warps) ----------------
__device__ __forceinline__ float warpMaxF(float v) {
    #pragma unroll
    for (int o = 16; o > 0; o >>= 1) v = fmaxf(v, __shfl_down_sync(0xffffffffu, v, o));
    return v;
}
__device__ __forceinline__ float warpSumF(float v) {
    #pragma unroll
    for (int o = 16; o > 0; o >>= 1) v += __shfl_down_sync(0xffffffffu, v, o);
    return v;
}
__device__ __forceinline__ int warpSumI(int v) {
    #pragma unroll
    for (int o = 16; o > 0; o >>= 1) v += __shfl_down_sync(0xffffffffu, v, o);
    return v;
}
__device__ float blockMaxF512(float v, float* smf) {
    int lane = threadIdx.x & 31, wid = threadIdx.x >> 5;
    v = warpMaxF(v);
    __syncthreads();
    if (lane == 0) smf[wid] = v;
    __syncthreads();
    if (wid == 0) {
        float t = (lane < 16) ? smf[lane] : -INFINITY;
        t = warpMaxF(t);
        if (lane == 0) smf[0] = t;
    }
    __syncthreads();
    return smf[0];
}
__device__ float blockSumF512(float v, float* smf) {
    int lane = threadIdx.x & 31, wid = threadIdx.x >> 5;
    v = warpSumF(v);
    __syncthreads();
    if (lane == 0) smf[wid] = v;
    __syncthreads();
    if (wid == 0) {
        float t = (lane < 16) ? smf[lane] : 0.0f;
        t = warpSumF(t);
        if (lane == 0) smf[0] = t;
    }
    __syncthreads();
    return smf[0];
}
__device__ int blockSumI512(int v, int* smi) {
    int lane = threadIdx.x & 31, wid = threadIdx.x >> 5;
    v = warpSumI(v);
    __syncthreads();
    if (lane == 0) smi[wid] = v;
    __syncthreads();
    if (wid == 0) {
        int t = (lane < 16) ? smi[lane] : 0;
        t = warpSumI(t);
        if (lane == 0) smi[16] = t;
    }
    __syncthreads();
    return smi[16];
}
__device__ int blockScanExclI512(int v, int* smi) {
    int lane = threadIdx.x & 31, wid = threadIdx.x >> 5;
    int incl = v;
    #pragma unroll
    for (int o = 1; o < 32; o <<= 1) {
        int t = __shfl_up_sync(0xffffffffu, incl, o);
        if (lane >= o) incl += t;
    }
    __syncthreads();
    if (lane == 31) smi[wid] = incl;
    __syncthreads();
    if (wid == 0) {
        int t = (lane < 16) ? smi[lane] : 0;
        int inc2 = t;
        #pragma unroll
        for (int o = 1; o < 32; o <<= 1) {
            int u = __shfl_up_sync(0xffffffffu, inc2, o);
            if (lane >= o) inc2 += u;
        }
        if (lane < 16) smi[lane] = inc2 - t;
    }
    __syncthreads();
    return incl - v + smi[wid];
}
__device__ __forceinline__ unsigned f2ord(float f) {
    unsigned u = __float_as_uint(f);
    return (u & 0x80000000u) ? ~u : (u | 0x80000000u);
}

// ---------------- kernel: fused score + normalize + bf16 split (warp per token) ----------------
__global__ void convert_kernel(const float* __restrict__ x, const float* __restrict__ rt,
                               float* __restrict__ s) {
    int token = (blockIdx.x * blockDim.x + threadIdx.x) >> 5;
    int lane = threadIdx.x & 31;
    if (token >= B_ * N_) return;
    const float4* xr = (const float4*)(x + (size_t)token * D_);
    const float4* rr = (const float4*)rt;
    float4 v[8]; float dot = 0.f, ss = 0.f;
    #pragma unroll
    for (int i = 0; i < 8; i++) {
        v[i] = xr[lane + 32 * i];
        float4 r = rr[lane + 32 * i];
        dot += v[i].x * r.x + v[i].y * r.y + v[i].z * r.z + v[i].w * r.w;
        ss  += v[i].x * v[i].x + v[i].y * v[i].y + v[i].z * v[i].z + v[i].w * v[i].w;
    }
    #pragma unroll
    for (int o = 16; o > 0; o >>= 1) {
        dot += __shfl_down_sync(0xffffffffu, dot, o);
        ss  += __shfl_xor_sync(0xffffffffu, ss, o);
    }
    if (lane == 0) s[token] = dot;
    float sc = 32.0f / fmaxf(sqrtf(ss), 1e-12f);
    __nv_bfloat162* ph = (__nv_bfloat162*)(g_xhi + (size_t)token * D_);
    __nv_bfloat162* pl = (__nv_bfloat162*)(g_xlo + (size_t)token * D_);
    #pragma unroll
    for (int i = 0; i < 8; i++) {
        int e = lane + 32 * i;
        float a0 = v[i].x * sc, a1 = v[i].y * sc, a2 = v[i].z * sc, a3 = v[i].w * sc;
        __nv_bfloat162 h0, h1, l0, l1;
        h0.x = __float2bfloat16(a0); h0.y = __float2bfloat16(a1);
        h1.x = __float2bfloat16(a2); h1.y = __float2bfloat16(a3);
        l0.x = __float2bfloat16(a0 - __bfloat162float(h0.x));
        l0.y = __float2bfloat16(a1 - __bfloat162float(h0.y));
        l1.x = __float2bfloat16(a2 - __bfloat162float(h1.x));
        l1.y = __float2bfloat16(a3 - __bfloat162float(h1.y));
        ph[2 * e] = h0; ph[2 * e + 1] = h1;
        pl[2 * e] = l0; pl[2 * e + 1] = l1;
    }
}

// ---------------- kernel: weight transpose + gamma fold + split ----------------
__global__ void wsplit_kernel(const float* __restrict__ W, const float* __restrict__ gamma,
                              __nv_bfloat16* __restrict__ Thi, __nv_bfloat16* __restrict__ Tlo,
                              int K, int N) {
    __shared__ float t[32][33];
    int n0 = blockIdx.x * 32, k0 = blockIdx.y * 32;
    int tx = threadIdx.x, ty = threadIdx.y;
    #pragma unroll
    for (int j = 0; j < 4; j++) {
        int k = k0 + ty + j * 8;
        float g = gamma ? gamma[k] : 1.0f;
        t[ty + j * 8][tx] = W[(size_t)k * N + n0 + tx] * g;
    }
    __syncthreads();
    #pragma unroll
    for (int j = 0; j < 4; j++) {
        int n = n0 + ty + j * 8;
        float v = t[tx][ty + j * 8];
        __nv_bfloat16 h = __float2bfloat16(v);
        Thi[(size_t)n * K + k0 + tx] = h;
        Tlo[(size_t)n * K + k0 + tx] = __float2bfloat16(v - __bfloat162float(h));
    }
}

// ---------------- kernel: coordinate descent + exact tie-aware top-k (512 thr) --------
__global__ void __launch_bounds__(512) router_kernel(const float* __restrict__ s_glob,
                                                     int* __restrict__ sel) {
    __shared__ float smf[16];
    __shared__ int   smi[17];
    __shared__ float a_sh;
    const int tid = threadIdx.x;
    const int b   = blockIdx.x;
    const float* s = s_glob + (size_t)b * N_;

    float sv[16], bv[16];
    #pragma unroll
    for (int i = 0; i < 16; i++) { sv[i] = s[tid * 16 + i]; bv[i] = -sv[i]; }

    const float logk = logf(KEFF);
    float a = 0.f;
    for (int it = 0; it < NITERS; ++it) {
        float m = -INFINITY;
        #pragma unroll
        for (int i = 0; i < 16; i++) m = fmaxf(m, sv[i] + bv[i]);
        m = blockMaxF512(m, smf);
        // Kahan-compensated per-thread sum, then pairwise tree
        float sum = 0.f, comp = 0.f;
        #pragma unroll
        for (int i = 0; i < 16; i++) {
            float y = expf(sv[i] + bv[i] - m) - comp;
            float t = sum + y;
            comp = (t - sum) - y;
            sum = t;
        }
        sum = blockSumF512(sum, smf);
        if (tid == 0) a_sh = EPS_ * (logk - (m + logf(sum)));
        __syncthreads();
        a = a_sh;
        #pragma unroll
        for (int i = 0; i < 16; i++) bv[i] = -fmaxf(sv[i] + a, 0.0f);
    }

    unsigned ord[16];
    #pragma unroll
    for (int i = 0; i < 16; i++) ord[i] = f2ord(fminf(sv[i] + a, 0.0f));

    unsigned p = 0; int Cgt = 0;
    for (int bit = 31; bit >= 0; --bit) {
        unsigned cand = (p >> bit) | 1u;
        int c = 0;
        #pragma unroll
        for (int i = 0; i < 16; i++) c += ((ord[i] >> bit) == cand);
        c = blockSumI512(c, smi);
        if (Cgt + c >= KSEL) p |= (1u << bit);
        else                 Cgt += c;
    }
    const int need_eq = KSEL - Cgt;
    int eqc = 0; bool eqf[16];
    #pragma unroll
    for (int i = 0; i < 16; i++) { eqf[i] = (ord[i] == p); eqc += eqf[i] ? 1 : 0; }
    int eq_excl = blockScanExclI512(eqc, smi);
    bool self_[16]; int selc = 0; int eqrun = 0;
    #pragma unroll
    for (int i = 0; i < 16; i++) {
        bool sgt = ord[i] > p;
        bool se  = eqf[i] && (eq_excl + eqrun < need_eq);
        eqrun += eqf[i] ? 1 : 0;
        self_[i] = sgt || se;
        selc += self_[i] ? 1 : 0;
    }
    int slot = blockScanExclI512(selc, smi);
    #pragma unroll
    for (int i = 0; i < 16; i++)
        if (self_[i]) { sel[b * KSEL + slot] = b * N_ + tid * 16 + i; slot++; }
}

// ---------------- mma.sync split-bf16 GEMM; CTA tile 128x256, BK=64, 2 stages ---------
// Stage layout (144B rows): Ahi[128] @0 | Alo[128] @18432 | Bhi[256] @36864 | Blo[256] @73728
// D = Ahi*Bhi + Ahi*Blo + Alo*Bhi (fp32 accum)
// mode 0: OHi/OLo = split(gelu(acc+bias));  mode 1: OF = acc+bias;  mode 2: OF[cmap] += acc+bias
#define ROWB  144u
#define STG2  110592u          // 768 rows * 144B
#define GSM2  (2u * STG2)      // 221184 B

__global__ void __launch_bounds__(256, 1) gemm_mma(
    const __nv_bfloat16* __restrict__ Ahi, const __nv_bfloat16* __restrict__ Alo,
    const __nv_bfloat16* __restrict__ Bhi, const __nv_bfloat16* __restrict__ Blo,
    int K, const int* __restrict__ amap,
    const float* __restrict__ bias, int mode,
    __nv_bfloat16* __restrict__ OHi, __nv_bfloat16* __restrict__ OLo, int NldH,
    float* __restrict__ OF, const int* __restrict__ cmap)
{
    extern __shared__ char smraw[];
    const uint32_t smb = smem_u32(smraw);
    const int tid = threadIdx.x;
    const int lane = tid & 31, wid = tid >> 5;
    const int mwarp = wid >> 1, nwarp = wid & 1;    // 4(M) x 2(N); warp tile 32x128

    // ---- loader: 768 rows/stage, 3 per thread ----
    const char* src[3]; uint32_t dst[3];
    #pragma unroll
    for (int j = 0; j < 3; j++) {
        int job = tid + j * 256;
        int op, rr;
        if      (job < 128) { op = 0; rr = job; }
        else if (job < 256) { op = 1; rr = job - 128; }
        else if (job < 512) { op = 2; rr = job - 256; }
        else                { op = 3; rr = job - 512; }
        const __nv_bfloat16* base; int grow;
        if (op < 2) {
            grow = blockIdx.y * 128 + rr;
            if (amap) grow = amap[grow];
            base = op ? Alo : Ahi;
        } else {
            grow = blockIdx.x * 256 + rr;
            base = (op == 3) ? Blo : Bhi;
        }
        src[j] = (const char*)(base + (size_t)grow * K);
        uint32_t opoff = (op == 0) ? 0u : (op == 1) ? 18432u : (op == 2) ? 36864u : 73728u;
        dst[j] = smb + opoff + (uint32_t)rr * ROWB;
    }

    #define LD_CHUNK(kc, stoff) do { \
        _Pragma("unroll") for (int j_ = 0; j_ < 3; j_++) { \
            const char* s_ = src[j_] + (size_t)(kc) * 128; \
            uint32_t d_ = dst[j_] + (stoff); \
            _Pragma("unroll") for (int c_ = 0; c_ < 8; c_++) \
                cpa16(d_ + c_ * 16u, s_ + c_ * 16); \
        } \
        CP_COMMIT(); \
    } while (0)

    // ldmatrix lane addresses (within a stage)
    const uint32_t aoff = (uint32_t)((mwarp * 32 + (lane & 7) + ((lane >> 3) & 1) * 8) * ROWB
                                     + (lane >> 4) * 16);
    const uint32_t boff = (uint32_t)((nwarp * 128 + (lane >> 4) * 8 + (lane & 7)) * ROWB
                                     + ((lane >> 3) & 1) * 16);

    float acc[2][16][4];
    #pragma unroll
    for (int mt = 0; mt < 2; mt++)
        #pragma unroll
        for (int nt = 0; nt < 16; nt++)
            #pragma unroll
            for (int q = 0; q < 4; q++) acc[mt][nt][q] = 0.f;

    const int nk = K >> 6;
    LD_CHUNK(0, 0u);
    LD_CHUNK(1, STG2);

    for (int it = 0; it < nk; ++it) {
        if (it + 1 < nk) cp_wait1(); else cp_wait0();
        __syncthreads();
        const uint32_t st = smb + (uint32_t)(it & 1) * STG2;
        #pragma unroll
        for (int ks = 0; ks < 4; ks++) {
            const uint32_t kb = (uint32_t)ks * 32u;
            uint32_t ah[2][4], al[2][4];
            #pragma unroll
            for (int mt = 0; mt < 2; mt++) {
                LDSM4(ah[mt], st + (uint32_t)mt * (16u * ROWB) + kb + aoff);
                LDSM4(al[mt], st + 18432u + (uint32_t)mt * (16u * ROWB) + kb + aoff);
            }
            #pragma unroll
            for (int jp = 0; jp < 8; jp++) {
                uint32_t bh[4], bl[4];
                LDSM4(bh, st + 36864u + (uint32_t)jp * (16u * ROWB) + kb + boff);
                LDSM4(bl, st + 73728u + (uint32_t)jp * (16u * ROWB) + kb + boff);
                #pragma unroll
                for (int mt = 0; mt < 2; mt++) {
                    MMA16816(acc[mt][jp * 2 + 0], ah[mt], bh[0], bh[1]);
                    MMA16816(acc[mt][jp * 2 + 0], ah[mt], bl[0], bl[1]);
                    MMA16816(acc[mt][jp * 2 + 0], al[mt], bh[0], bh[1]);
                    MMA16816(acc[mt][jp * 2 + 1], ah[mt], bh[2], bh[3]);
                    MMA16816(acc[mt][jp * 2 + 1], ah[mt], bl[2], bl[3]);
                    MMA16816(acc[mt][jp * 2 + 1], al[mt], bh[2], bh[3]);
                }
            }
        }
        __syncthreads();
        if (it + 2 < nk) LD_CHUNK(it + 2, (uint32_t)(it & 1) * STG2);
    }

    // ---- epilogue ----
    const int mbase = mwarp * 32;
    const int cbase = blockIdx.x * 256 + nwarp * 128;
    #pragma unroll
    for (int mt = 0; mt < 2; mt++) {
        #pragma unroll
        for (int half = 0; half < 2; half++) {
            const int row  = mbase + mt * 16 + (lane >> 2) + half * 8;
            const int grow = blockIdx.y * 128 + row;
            if (mode == 0) {
                size_t obase = (size_t)grow * NldH;
                #pragma unroll
                for (int nt = 0; nt < 16; nt++) {
                    const int gc = cbase + nt * 8 + (lane & 3) * 2;
                    float v0 = acc[mt][nt][half * 2 + 0] + __ldg(&bias[gc]);
                    float v1 = acc[mt][nt][half * 2 + 1] + __ldg(&bias[gc + 1]);
                    float g0 = gelu_exact(v0), g1 = gelu_exact(v1);
                    __nv_bfloat162 h2, l2;
                    h2.x = __float2bfloat16(g0); h2.y = __float2bfloat16(g1);
                    l2.x = __float2bfloat16(g0 - __bfloat162float(h2.x));
                    l2.y = __float2bfloat16(g1 - __bfloat162float(h2.y));
                    *(__nv_bfloat162*)(OHi + obase + gc) = h2;
                    *(__nv_bfloat162*)(OLo + obase + gc) = l2;
                }
            } else if (mode == 1) {
                float* po = OF + (size_t)grow * 1024;
                #pragma unroll
                for (int nt = 0; nt < 16; nt++) {
                    const int gc = cbase + nt * 8 + (lane & 3) * 2;
                    float2 w;
                    w.x = acc[mt][nt][half * 2 + 0] + __ldg(&bias[gc]);
                    w.y = acc[mt][nt][half * 2 + 1] + __ldg(&bias[gc + 1]);
                    *(float2*)(po + gc) = w;
                }
            } else {
                const int orow = cmap[grow];
                float* po = OF + (size_t)orow * 1024;
                #pragma unroll
                for (int nt = 0; nt < 16; nt++) {
                    const int gc = cbase + nt * 8 + (lane & 3) * 2;
                    float2 o = *(float2*)(po + gc);
                    o.x += acc[mt][nt][half * 2 + 0] + __ldg(&bias[gc]);
                    o.y += acc[mt][nt][half * 2 + 1] + __ldg(&bias[gc + 1]);
                    *(float2*)(po + gc) = o;
                }
            }
        }
    }
    #undef LD_CHUNK
}

// ---------------- launch ----------------
extern "C" void kernel_launch(void* const* d_in, const int* in_sizes, int n_in,
                              void* d_out, int out_size) {
    const float* x    = (const float*)d_in[0];
    const float* rt   = (const float*)d_in[1];
    const float* lgam = (const float*)d_in[2];
    const float* lw1  = (const float*)d_in[3];
    const float* lb1  = (const float*)d_in[4];
    const float* lw2  = (const float*)d_in[5];
    const float* lb2  = (const float*)d_in[6];
    const float* hgam = (const float*)d_in[7];
    const float* hw1  = (const float*)d_in[8];
    const float* hb1  = (const float*)d_in[9];
    const float* hw2  = (const float*)d_in[10];
    const float* hb2  = (const float*)d_in[11];
    float* out = (float*)d_out;

    cudaFuncSetAttribute(gemm_mma, cudaFuncAttributeMaxDynamicSharedMemorySize, GSM2);

    void *s_p, *sel_p, *xhi, *xlo, *w1lh, *w1ll, *w2lh, *w2ll, *w1hh, *w1hl, *w2hh, *w2hl,
         *hlh, *hll, *hhh, *hhl;
    cudaGetSymbolAddress(&s_p, g_s);       cudaGetSymbolAddress(&sel_p, g_sel);
    cudaGetSymbolAddress(&xhi, g_xhi);     cudaGetSymbolAddress(&xlo, g_xlo);
    cudaGetSymbolAddress(&w1lh, g_w1l_hi); cudaGetSymbolAddress(&w1ll, g_w1l_lo);
    cudaGetSymbolAddress(&w2lh, g_w2l_hi); cudaGetSymbolAddress(&w2ll, g_w2l_lo);
    cudaGetSymbolAddress(&w1hh, g_w1h_hi); cudaGetSymbolAddress(&w1hl, g_w1h_lo);
    cudaGetSymbolAddress(&w2hh, g_w2h_hi); cudaGetSymbolAddress(&w2hl, g_w2h_lo);
    cudaGetSymbolAddress(&hlh, g_hl_hi);   cudaGetSymbolAddress(&hll, g_hl_lo);
    cudaGetSymbolAddress(&hhh, g_hh_hi);   cudaGetSymbolAddress(&hhl, g_hh_lo);

    dim3 wb(32, 8);
    wsplit_kernel<<<dim3(DL_/32, D_/32), wb>>>(lw1, lgam, (__nv_bfloat16*)w1lh, (__nv_bfloat16*)w1ll, D_, DL_);
    wsplit_kernel<<<dim3(D_/32, DL_/32), wb>>>(lw2, nullptr, (__nv_bfloat16*)w2lh, (__nv_bfloat16*)w2ll, DL_, D_);
    wsplit_kernel<<<dim3(DH_/32, D_/32), wb>>>(hw1, hgam, (__nv_bfloat16*)w1hh, (__nv_bfloat16*)w1hl, D_, DH_);
    wsplit_kernel<<<dim3(D_/32, DH_/32), wb>>>(hw2, nullptr, (__nv_bfloat16*)w2hh, (__nv_bfloat16*)w2hl, DH_, D_);

    convert_kernel<<<(B_ * N_) / 8, 256>>>(x, rt, (float*)s_p);
    router_kernel<<<B_, 512>>>((const float*)s_p, (int*)sel_p);

    // light: hidden = gelu(xn @ (g*W1) + b1); out = hidden @ W2 + b2
    gemm_mma<<<dim3(DL_/256, (B_*N_)/128), 256, GSM2>>>(
        (__nv_bfloat16*)xhi, (__nv_bfloat16*)xlo, (__nv_bfloat16*)w1lh, (__nv_bfloat16*)w1ll,
        D_, nullptr, lb1, 0, (__nv_bfloat16*)hlh, (__nv_bfloat16*)hll, DL_, nullptr, nullptr);
    gemm_mma<<<dim3(D_/256, (B_*N_)/128), 256, GSM2>>>(
        (__nv_bfloat16*)hlh, (__nv_bfloat16*)hll, (__nv_bfloat16*)w2lh, (__nv_bfloat16*)w2ll,
        DL_, nullptr, lb2, 1, nullptr, nullptr, 0, out, nullptr);

    // heavy: gathered rows -> hidden -> scatter-accumulate into out
    gemm_mma<<<dim3(DH_/256, (B_*KSEL)/128), 256, GSM2>>>(
        (__nv_bfloat16*)xhi, (__nv_bfloat16*)xlo, (__nv_bfloat16*)w1hh, (__nv_bfloat16*)w1hl,
        D_, (const int*)sel_p, hb1, 0, (__nv_bfloat16*)hhh, (__nv_bfloat16*)hhl, DH_, nullptr, nullptr);
    gemm_mma<<<dim3(D_/256, (B_*KSEL)/128), 256, GSM2>>>(
        (__nv_bfloat16*)hhh, (__nv_bfloat16*)hhl, (__nv_bfloat16*)w2hh, (__nv_bfloat16*)w2hl,
        DH_, nullptr, hb2, 2, nullptr, nullptr, 0, out, (const int*)sel_p);
}